// round 6
// baseline (speedup 1.0000x reference)
#include <cuda_runtime.h>
#include <cuda_fp16.h>
#include <cstdint>

// Conv (32,64,64,128) NHWC fp32 * w(256,1152) + b -> out (32,62,62,256) fp32.
// Implicit GEMM on mma.sync m16n8k16 fp16 (fp32 accumulate).
// M = 123008 = 961*128, N = 256 (2 CTA tiles of 128), K = 1152 = 18 chunks of 64.
// 128 threads/CTA, 4 warps (2x2), warp tile 64x64; 2 CTAs/SM resident.

#define H_IN 64
#define W_IN 64
#define C_IN 128
#define F_OUT 256
#define HO 62
#define WO 62
#define KDIM 1152
#define BM 128
#define BN 128
#define CK 64
#define NCHUNK 18
#define STAGES 3
#define THREADS 128

#define A_BYTES (BM * CK * 2)              // 16384
#define B_BYTES (BN * CK * 2)              // 16384
#define OFF_A 0
#define OFF_B (A_BYTES)
#define STAGE_SZ (A_BYTES + B_BYTES)       // 32768
#define SMEM_TOTAL (STAGES * STAGE_SZ)     // 98304

#define IN_ELEMS (32 * 64 * 64 * 128)
#define W_ELEMS (F_OUT * KDIM)

__device__ __align__(16) __half g_inH[IN_ELEMS];
__device__ __align__(16) __half g_wH[W_ELEMS];

// ---------------- helpers ----------------
__device__ __forceinline__ uint32_t smem_u32(const void* p) {
    uint32_t a;
    asm("{ .reg .u64 t; cvta.to.shared.u64 t, %1; cvt.u32.u64 %0, t; }"
        : "=r"(a) : "l"(p));
    return a;
}

__device__ __forceinline__ void cpa16(uint32_t dst, const void* src) {
    asm volatile("cp.async.cg.shared.global [%0], [%1], 16;"
                 :: "r"(dst), "l"(src));
}
#define CP_COMMIT() asm volatile("cp.async.commit_group;" ::: "memory")
#define CP_WAIT1()  asm volatile("cp.async.wait_group 1;" ::: "memory")
#define CP_WAIT0()  asm volatile("cp.async.wait_group 0;" ::: "memory")

__device__ __forceinline__ void ldm4(uint32_t* r, uint32_t a) {
    asm volatile("ldmatrix.sync.aligned.m8n8.x4.shared.b16 {%0,%1,%2,%3}, [%4];"
                 : "=r"(r[0]), "=r"(r[1]), "=r"(r[2]), "=r"(r[3]) : "r"(a));
}

__device__ __forceinline__ void mma16816(float* c, const uint32_t* a,
                                         uint32_t b0, uint32_t b1) {
    asm volatile(
        "mma.sync.aligned.m16n8k16.row.col.f32.f16.f16.f32 "
        "{%0,%1,%2,%3}, {%4,%5,%6,%7}, {%8,%9}, {%0,%1,%2,%3};"
        : "+f"(c[0]), "+f"(c[1]), "+f"(c[2]), "+f"(c[3])
        : "r"(a[0]), "r"(a[1]), "r"(a[2]), "r"(a[3]), "r"(b0), "r"(b1));
}

__device__ __forceinline__ uint2 cvt4(float4 v) {
    __half2 p0 = __floats2half2_rn(v.x, v.y);
    __half2 p1 = __floats2half2_rn(v.z, v.w);
    uint2 r;
    r.x = *reinterpret_cast<uint32_t*>(&p0);
    r.y = *reinterpret_cast<uint32_t*>(&p1);
    return r;
}

// ---------------- pre-pass: fp32 -> fp16 (16B stores) ----------------
__global__ void cvt_input(const float4* __restrict__ src) {
    const int n8 = IN_ELEMS / 8;
    const int stride = gridDim.x * blockDim.x;
    uint4* h = reinterpret_cast<uint4*>(g_inH);
    for (int i = blockIdx.x * blockDim.x + threadIdx.x; i < n8; i += stride) {
        uint2 a = cvt4(src[i * 2]);
        uint2 b = cvt4(src[i * 2 + 1]);
        uint4 v; v.x = a.x; v.y = a.y; v.z = b.x; v.w = b.y;
        h[i] = v;
    }
}

__global__ void cvt_weights(const float4* __restrict__ src) {
    const int n8 = W_ELEMS / 8;
    const int stride = gridDim.x * blockDim.x;
    uint4* h = reinterpret_cast<uint4*>(g_wH);
    for (int i = blockIdx.x * blockDim.x + threadIdx.x; i < n8; i += stride) {
        uint2 a = cvt4(src[i * 2]);
        uint2 b = cvt4(src[i * 2 + 1]);
        uint4 v; v.x = a.x; v.y = a.y; v.z = b.x; v.w = b.y;
        h[i] = v;
    }
}

// ---------------- main GEMM ----------------
// Rows are 128B = 8 x 16B chunks; swizzle: chunk c -> c ^ (row & 7).
__device__ __forceinline__ void prefetch_stage(uint32_t sb, int stage, int ch,
                                               const __half* aptr,
                                               const __half* bptr, int tid) {
    // aptr = g_inH + arow (tap-0 base for row tid); bptr = g_wH + f*KDIM.
    const int p     = ch >> 1;              // filter tap 0..8
    const int chalf = (ch & 1) * 64;        // channel offset within tap
    const int kh = p / 3, kw = p - kh * 3;
    const long a_off = (long)(kh * W_IN + kw) * C_IN + chalf;
    const int  k0    = ch * CK;
    const uint32_t st = sb + stage * STAGE_SZ;
    const uint32_t rb = tid * 128;
    const int      rs = tid & 7;

#pragma unroll
    for (int c = 0; c < 8; c++) {
        const int cs = c ^ rs;
        cpa16(st + OFF_A + rb + cs * 16, aptr + a_off + c * 8);
        cpa16(st + OFF_B + rb + cs * 16, bptr + k0 + c * 8);
    }
}

__global__ __launch_bounds__(THREADS, 2)
void conv_gemm_hmma(const float* __restrict__ bias, float* __restrict__ out) {
    extern __shared__ char smem[];
    const uint32_t sb = smem_u32(smem);
    const int tid  = threadIdx.x;
    const int lane = tid & 31;
    const int wid  = tid >> 5;
    const int warpM = wid >> 1;    // 0..1 -> 64-row slab
    const int warpN = wid & 1;     // 0..1 -> 64-col slab
    const int m_base = blockIdx.x * BM;
    const int n_base = blockIdx.y * BN;

    // gmem base of this thread's loader rows (tile row = tid)
    const int m_ar = m_base + tid;
    const int nimg = m_ar / (HO * WO);
    const int rem  = m_ar - nimg * (HO * WO);
    const int ho   = rem / WO;
    const int wo   = rem - ho * WO;
    const __half* aptr = g_inH + ((long)(nimg * H_IN + ho) * W_IN + wo) * C_IN;
    const __half* bptr = g_wH + (long)(n_base + tid) * KDIM;

    float acc[4][8][4];
#pragma unroll
    for (int i = 0; i < 4; i++)
#pragma unroll
        for (int j = 0; j < 8; j++)
#pragma unroll
            for (int k = 0; k < 4; k++) acc[i][j][k] = 0.0f;

    // prologue: fill STAGES-1 = 2 stages
#pragma unroll
    for (int s = 0; s < STAGES - 1; s++) {
        prefetch_stage(sb, s, s, aptr, bptr, tid);
        CP_COMMIT();
    }

    int stage = 0;
    for (int ch = 0; ch < NCHUNK; ch++) {
        CP_WAIT1();
        __syncthreads();   // stage (ch) data visible; previous stage free

        const int pf = ch + STAGES - 1;
        int pstage = stage + STAGES - 1; if (pstage >= STAGES) pstage -= STAGES;
        if (pf < NCHUNK) prefetch_stage(sb, pstage, pf, aptr, bptr, tid);
        CP_COMMIT();

        const uint32_t st = sb + stage * STAGE_SZ;
#pragma unroll
        for (int s = 0; s < 4; s++) {          // four k16 steps per 64-chunk
            uint32_t ah[4][4], bh[4][4];
            const int c  = s * 2 + (lane >> 4);
            const int rl = lane & 15;
#pragma unroll
            for (int mb = 0; mb < 4; mb++) {
                const int row = warpM * 64 + mb * 16 + rl;
                const int cs  = c ^ (row & 7);
                ldm4(ah[mb], st + OFF_A + row * 128 + cs * 16);
            }
#pragma unroll
            for (int i = 0; i < 4; i++) {
                const int row = warpN * 64 + i * 16 + rl;
                const int cs  = c ^ (row & 7);
                ldm4(bh[i], st + OFF_B + row * 128 + cs * 16);
            }
#pragma unroll
            for (int mb = 0; mb < 4; mb++)
#pragma unroll
                for (int i = 0; i < 4; i++)
#pragma unroll
                    for (int h = 0; h < 2; h++)
                        mma16816(acc[mb][i * 2 + h], ah[mb],
                                 bh[i][h], bh[i][h + 2]);
        }
        stage++; if (stage == STAGES) stage = 0;
    }
    CP_WAIT0();

    // ---- epilogue: bias + fp32 stores ----
#pragma unroll
    for (int nb = 0; nb < 8; nb++) {
        const int n = n_base + warpN * 64 + nb * 8 + (lane & 3) * 2;
        const float2 bv = *reinterpret_cast<const float2*>(bias + n);
#pragma unroll
        for (int mb = 0; mb < 4; mb++) {
            const long m0 = (long)m_base + warpM * 64 + mb * 16 + (lane >> 2);
            const float* c = acc[mb][nb];
            float2 v0, v1;
            v0.x = c[0] + bv.x; v0.y = c[1] + bv.y;
            v1.x = c[2] + bv.x; v1.y = c[3] + bv.y;
            *reinterpret_cast<float2*>(out + m0 * F_OUT + n)       = v0;
            *reinterpret_cast<float2*>(out + (m0 + 8) * F_OUT + n) = v1;
        }
    }
}

extern "C" void kernel_launch(void* const* d_in, const int* in_sizes, int n_in,
                              void* d_out, int out_size) {
    const float* in   = (const float*)d_in[0];
    const float* w    = (const float*)d_in[1];
    const float* bias = (const float*)d_in[2];
    float* out        = (float*)d_out;

    cvt_input<<<2048, 256>>>((const float4*)in);
    cvt_weights<<<144, 256>>>((const float4*)w);

    cudaFuncSetAttribute(conv_gemm_hmma,
                         cudaFuncAttributeMaxDynamicSharedMemorySize, SMEM_TOTAL);
    dim3 grid(961, 2);
    conv_gemm_hmma<<<grid, THREADS, SMEM_TOTAL>>>(bias, out);
}

// round 7
// speedup vs baseline: 1.4019x; 1.4019x over previous
#include <cuda_runtime.h>
#include <cuda_fp16.h>
#include <cstdint>

// Conv (32,64,64,128) NHWC fp32 * w(256,1152) + b -> out (32,62,62,256) fp32.
// Implicit GEMM on mma.sync m16n8k16 fp16 (fp32 accumulate).
// M = 123008 = 961*128, N = 256 (2 CTA tiles of 128), K = 1152 = 18 chunks of 64.
// GEMM config = round-5 optimum: 256 thr/CTA, 8 warps (2x4), warp tile 64x32,
// 3-stage cp.async pipeline, 2 CTAs/SM resident (96KB smem, <=128 regs).
// Prepass: single fused fp32->fp16 kernel, 8-way ILP (latency-bound fix).

#define H_IN 64
#define W_IN 64
#define C_IN 128
#define F_OUT 256
#define HO 62
#define WO 62
#define KDIM 1152
#define BM 128
#define BN 128
#define CK 64
#define NCHUNK 18
#define STAGES 3
#define THREADS 256

#define A_BYTES (BM * CK * 2)              // 16384
#define B_BYTES (BN * CK * 2)              // 16384
#define OFF_A 0
#define OFF_B (A_BYTES)
#define STAGE_SZ (A_BYTES + B_BYTES)       // 32768
#define SMEM_TOTAL (STAGES * STAGE_SZ)     // 98304

#define IN_ELEMS (32 * 64 * 64 * 128)
#define W_ELEMS (F_OUT * KDIM)
#define IN_V4 (IN_ELEMS / 8)               // 4194304 uint4 outputs
#define W_V4  (W_ELEMS / 8)                // 36864
#define CVT_UN 8
#define CVT_TPB 256
#define CVT_IN_BLOCKS  (IN_V4 / (CVT_TPB * CVT_UN))   // 2048
#define CVT_W_UN 4
#define CVT_W_BLOCKS   (W_V4 / (CVT_TPB * CVT_W_UN))  // 36

__device__ __align__(16) __half g_inH[IN_ELEMS];
__device__ __align__(16) __half g_wH[W_ELEMS];

// ---------------- helpers ----------------
__device__ __forceinline__ uint32_t smem_u32(const void* p) {
    uint32_t a;
    asm("{ .reg .u64 t; cvta.to.shared.u64 t, %1; cvt.u32.u64 %0, t; }"
        : "=r"(a) : "l"(p));
    return a;
}

__device__ __forceinline__ void cpa16(uint32_t dst, const void* src) {
    asm volatile("cp.async.cg.shared.global [%0], [%1], 16;"
                 :: "r"(dst), "l"(src));
}
#define CP_COMMIT() asm volatile("cp.async.commit_group;" ::: "memory")
#define CP_WAIT1()  asm volatile("cp.async.wait_group 1;" ::: "memory")
#define CP_WAIT0()  asm volatile("cp.async.wait_group 0;" ::: "memory")

__device__ __forceinline__ void ldm4(uint32_t* r, uint32_t a) {
    asm volatile("ldmatrix.sync.aligned.m8n8.x4.shared.b16 {%0,%1,%2,%3}, [%4];"
                 : "=r"(r[0]), "=r"(r[1]), "=r"(r[2]), "=r"(r[3]) : "r"(a));
}

__device__ __forceinline__ void mma16816(float* c, const uint32_t* a,
                                         uint32_t b0, uint32_t b1) {
    asm volatile(
        "mma.sync.aligned.m16n8k16.row.col.f32.f16.f16.f32 "
        "{%0,%1,%2,%3}, {%4,%5,%6,%7}, {%8,%9}, {%0,%1,%2,%3};"
        : "+f"(c[0]), "+f"(c[1]), "+f"(c[2]), "+f"(c[3])
        : "r"(a[0]), "r"(a[1]), "r"(a[2]), "r"(a[3]), "r"(b0), "r"(b1));
}

__device__ __forceinline__ uint4 cvt8(float4 v0, float4 v1) {
    __half2 p0 = __floats2half2_rn(v0.x, v0.y);
    __half2 p1 = __floats2half2_rn(v0.z, v0.w);
    __half2 p2 = __floats2half2_rn(v1.x, v1.y);
    __half2 p3 = __floats2half2_rn(v1.z, v1.w);
    uint4 r;
    r.x = *reinterpret_cast<uint32_t*>(&p0);
    r.y = *reinterpret_cast<uint32_t*>(&p1);
    r.z = *reinterpret_cast<uint32_t*>(&p2);
    r.w = *reinterpret_cast<uint32_t*>(&p3);
    return r;
}

// ---------------- fused pre-pass: fp32 -> fp16, high-ILP ----------------
__global__ __launch_bounds__(CVT_TPB)
void cvt_all(const float4* __restrict__ in, const float4* __restrict__ w) {
    const int b = blockIdx.x;
    if (b < CVT_IN_BLOCKS) {
        uint4* h = reinterpret_cast<uint4*>(g_inH);
        const int base = b * CVT_TPB * CVT_UN + threadIdx.x;
        float4 s[CVT_UN][2];
#pragma unroll
        for (int u = 0; u < CVT_UN; u++) {
            const int i = base + u * CVT_TPB;
            s[u][0] = in[i * 2];
            s[u][1] = in[i * 2 + 1];
        }
#pragma unroll
        for (int u = 0; u < CVT_UN; u++)
            h[base + u * CVT_TPB] = cvt8(s[u][0], s[u][1]);
    } else {
        uint4* h = reinterpret_cast<uint4*>(g_wH);
        const int base = (b - CVT_IN_BLOCKS) * CVT_TPB * CVT_W_UN + threadIdx.x;
        float4 s[CVT_W_UN][2];
#pragma unroll
        for (int u = 0; u < CVT_W_UN; u++) {
            const int i = base + u * CVT_TPB;
            s[u][0] = w[i * 2];
            s[u][1] = w[i * 2 + 1];
        }
#pragma unroll
        for (int u = 0; u < CVT_W_UN; u++)
            h[base + u * CVT_TPB] = cvt8(s[u][0], s[u][1]);
    }
}

// ---------------- main GEMM (round-5 validated config) ----------------
// Rows are 128B = 8 x 16B chunks; swizzle: chunk c -> c ^ (row & 7).
__device__ __forceinline__ void prefetch_stage(uint32_t sb, int stage, int ch,
                                               const __half* aptr,
                                               const __half* bptr, int tid) {
    const int p     = ch >> 1;              // filter tap 0..8
    const int chalf = (ch & 1) * 64;        // channel offset within tap
    const int kh = p / 3, kw = p - kh * 3;
    const long a_off = (long)(kh * W_IN + kw) * C_IN + chalf;
    const int  k0    = ch * CK;
    const uint32_t st = sb + stage * STAGE_SZ;

    const int row = tid >> 1;
    const int h   = tid & 1;
#pragma unroll
    for (int j = 0; j < 4; j++) {
        const int c  = h * 4 + j;
        const int cs = c ^ (row & 7);
        cpa16(st + OFF_A + row * 128 + cs * 16, aptr + a_off + c * 8);
        cpa16(st + OFF_B + row * 128 + cs * 16, bptr + k0 + c * 8);
    }
}

__global__ __launch_bounds__(THREADS, 2)
void conv_gemm_hmma(const float* __restrict__ bias, float* __restrict__ out) {
    extern __shared__ char smem[];
    const uint32_t sb = smem_u32(smem);
    const int tid  = threadIdx.x;
    const int lane = tid & 31;
    const int wid  = tid >> 5;
    const int warpM = wid >> 2;    // 0..1 -> 64-row slab
    const int warpN = wid & 3;     // 0..3 -> 32-col slab
    const int m_base = blockIdx.x * BM;
    const int n_base = blockIdx.y * BN;

    // gmem base of this thread's A row (tile row = tid>>1)
    const int m_ar = m_base + (tid >> 1);
    const int nimg = m_ar / (HO * WO);
    const int rem  = m_ar - nimg * (HO * WO);
    const int ho   = rem / WO;
    const int wo   = rem - ho * WO;
    const __half* aptr = g_inH + ((long)(nimg * H_IN + ho) * W_IN + wo) * C_IN;
    const __half* bptr = g_wH + (long)(n_base + (tid >> 1)) * KDIM;

    float acc[4][4][4];
#pragma unroll
    for (int i = 0; i < 4; i++)
#pragma unroll
        for (int j = 0; j < 4; j++)
#pragma unroll
            for (int k = 0; k < 4; k++) acc[i][j][k] = 0.0f;

    // prologue: fill STAGES-1 = 2 stages
#pragma unroll
    for (int s = 0; s < STAGES - 1; s++) {
        prefetch_stage(sb, s, s, aptr, bptr, tid);
        CP_COMMIT();
    }

    int stage = 0;
    for (int ch = 0; ch < NCHUNK; ch++) {
        CP_WAIT1();
        __syncthreads();   // stage (ch) data visible; previous stage free

        const int pf = ch + STAGES - 1;
        int pstage = stage + STAGES - 1; if (pstage >= STAGES) pstage -= STAGES;
        if (pf < NCHUNK) prefetch_stage(sb, pstage, pf, aptr, bptr, tid);
        CP_COMMIT();

        const uint32_t st = sb + stage * STAGE_SZ;
#pragma unroll
        for (int s = 0; s < 4; s++) {          // four k16 steps per 64-chunk
            uint32_t ah[4][4], bh[2][4];
#pragma unroll
            for (int mb = 0; mb < 4; mb++) {
                const int row = warpM * 64 + mb * 16 + (lane & 15);
                const int c   = s * 2 + (lane >> 4);
                const int cs  = c ^ (row & 7);
                ldm4(ah[mb], st + OFF_A + row * 128 + cs * 16);
            }
#pragma unroll
            for (int i = 0; i < 2; i++) {
                const int row = warpN * 32 + i * 16 + (lane & 15);
                const int c   = s * 2 + (lane >> 4);
                const int cs  = c ^ (row & 7);
                ldm4(bh[i], st + OFF_B + row * 128 + cs * 16);
            }
#pragma unroll
            for (int mb = 0; mb < 4; mb++)
#pragma unroll
                for (int i = 0; i < 2; i++)
#pragma unroll
                    for (int h = 0; h < 2; h++)
                        mma16816(acc[mb][i * 2 + h], ah[mb],
                                 bh[i][h], bh[i][h + 2]);
        }
        stage++; if (stage == STAGES) stage = 0;
    }
    CP_WAIT0();

    // ---- epilogue: bias + fp32 stores ----
#pragma unroll
    for (int nb = 0; nb < 4; nb++) {
        const int n = n_base + warpN * 32 + nb * 8 + (lane & 3) * 2;
        const float2 bv = *reinterpret_cast<const float2*>(bias + n);
#pragma unroll
        for (int mb = 0; mb < 4; mb++) {
            const long m0 = (long)m_base + warpM * 64 + mb * 16 + (lane >> 2);
            const float* c = acc[mb][nb];
            float2 v0, v1;
            v0.x = c[0] + bv.x; v0.y = c[1] + bv.y;
            v1.x = c[2] + bv.x; v1.y = c[3] + bv.y;
            *reinterpret_cast<float2*>(out + m0 * F_OUT + n)       = v0;
            *reinterpret_cast<float2*>(out + (m0 + 8) * F_OUT + n) = v1;
        }
    }
}

extern "C" void kernel_launch(void* const* d_in, const int* in_sizes, int n_in,
                              void* d_out, int out_size) {
    const float* in   = (const float*)d_in[0];
    const float* w    = (const float*)d_in[1];
    const float* bias = (const float*)d_in[2];
    float* out        = (float*)d_out;

    cvt_all<<<CVT_IN_BLOCKS + CVT_W_BLOCKS, CVT_TPB>>>(
        (const float4*)in, (const float4*)w);

    cudaFuncSetAttribute(conv_gemm_hmma,
                         cudaFuncAttributeMaxDynamicSharedMemorySize, SMEM_TOTAL);
    dim3 grid(961, 2);
    conv_gemm_hmma<<<grid, THREADS, SMEM_TOTAL>>>(bias, out);
}